// round 1
// baseline (speedup 1.0000x reference)
#include <cuda_runtime.h>
#include <math.h>

#define NN   65536
#define DD   128
#define EE   524288
#define BB   128
#define NPER 512

// ---------------- scratch (device globals; no allocs allowed) ----------------
__device__ int   g_cnt[NN];
__device__ int   g_rowptr[NN + 1];
__device__ int   g_fill[NN];
__device__ int   g_csr[EE];
__device__ float g_x[NN * DD];      // current node features (post-pool)
__device__ float g_mean[NN * DD];   // aggregated neighbor mean
__device__ float g_h[NN * DD];      // SAGE output (pre-pool)
__device__ unsigned char g_nm[NN];  // node mask
__device__ float g_z[BB * 256];     // summed readouts

// ---------------- init: copy x, mask=1, z=0 ----------------
__global__ void k_init(const float* __restrict__ x) {
    int idx = blockIdx.x * blockDim.x + threadIdx.x;   // exactly N*D threads
    g_x[idx] = x[idx];
    if (idx < NN) g_nm[idx] = 1;
    if (idx < BB * 256) g_z[idx] = 0.f;
}

__global__ void k_zero_cnt() {
    int i = blockIdx.x * blockDim.x + threadIdx.x;     // exactly N threads
    g_cnt[i] = 0;
}

__global__ void k_hist(const int* __restrict__ dst) {
    int e = blockIdx.x * blockDim.x + threadIdx.x;     // exactly E threads
    atomicAdd(&g_cnt[dst[e]], 1);
}

// one block, 1024 threads, each owns 64 contiguous counts
__global__ void k_scan() {
    int t = threadIdx.x;
    int base = t * 64;
    int local = 0;
#pragma unroll 8
    for (int i = 0; i < 64; i++) local += g_cnt[base + i];

    __shared__ int sh[1024];
    sh[t] = local;
    __syncthreads();
    for (int off = 1; off < 1024; off <<= 1) {
        int v = (t >= off) ? sh[t - off] : 0;
        __syncthreads();
        sh[t] += v;
        __syncthreads();
    }
    int run = sh[t] - local;   // exclusive prefix
    for (int i = 0; i < 64; i++) {
        g_rowptr[base + i] = run;
        g_fill[base + i]   = run;
        run += g_cnt[base + i];
    }
    if (t == 1023) g_rowptr[NN] = run;
}

__global__ void k_scatter(const int* __restrict__ src, const int* __restrict__ dst) {
    int e = blockIdx.x * blockDim.x + threadIdx.x;     // exactly E threads
    int p = atomicAdd(&g_fill[dst[e]], 1);
    g_csr[p] = src[e];
}

// ---------------- neighbor mean: one warp per dst node ----------------
__global__ void k_aggregate() {
    int node = blockIdx.x * 8 + (threadIdx.x >> 5);
    int lane = threadIdx.x & 31;
    float4 acc = make_float4(0.f, 0.f, 0.f, 0.f);
    float4* Mout = reinterpret_cast<float4*>(g_mean);
    if (!g_nm[node]) { Mout[node * 32 + lane] = acc; return; }
    int r0 = g_rowptr[node], r1 = g_rowptr[node + 1];
    const float4* X = reinterpret_cast<const float4*>(g_x);
    int deg = 0;
    for (int e = r0; e < r1; e++) {
        int s = g_csr[e];
        if (g_nm[s]) {
            float4 v = X[s * 32 + lane];
            acc.x += v.x; acc.y += v.y; acc.z += v.z; acc.w += v.w;
            deg++;
        }
    }
    float inv = 1.f / (float)(deg > 1 ? deg : 1);
    acc.x *= inv; acc.y *= inv; acc.z *= inv; acc.w *= inv;
    Mout[node * 32 + lane] = acc;
}

// ---------------- fused SAGE GEMM: h = relu(mean@wl^T + x@wr^T + bl) --------
// 128x128 output tile per block, 256 threads, 8x8 per thread (split 4+4 frags)
__global__ __launch_bounds__(256) void k_gemm(
    const float* __restrict__ wl, const float* __restrict__ wr,
    const float* __restrict__ bl)
{
    __shared__ __align__(16) float As[16][132];
    __shared__ __align__(16) float Ws[16][132];

    int t = threadIdx.x;
    int tx4 = (t & 15) * 4;
    int ty4 = (t >> 4) * 4;
    int base = blockIdx.x * 128;
    int kidx = t & 15;
    int rbase = t >> 4;

    float acc[8][8];
#pragma unroll
    for (int i = 0; i < 8; i++)
#pragma unroll
        for (int j = 0; j < 8; j++) acc[i][j] = 0.f;

    for (int phase = 0; phase < 2; phase++) {
        const float* Ap = phase ? g_x : g_mean;
        const float* Wp = phase ? wr : wl;
        for (int kc = 0; kc < 128; kc += 16) {
            __syncthreads();
#pragma unroll
            for (int jj = 0; jj < 8; jj++) {
                int row = rbase + jj * 16;
                As[kidx][row] = Ap[(base + row) * 128 + kc + kidx];
                Ws[kidx][row] = Wp[row * 128 + kc + kidx];
            }
            __syncthreads();
#pragma unroll
            for (int kk = 0; kk < 16; kk++) {
                float a[8], b[8];
                *reinterpret_cast<float4*>(a)     = *reinterpret_cast<const float4*>(&As[kk][ty4]);
                *reinterpret_cast<float4*>(a + 4) = *reinterpret_cast<const float4*>(&As[kk][64 + ty4]);
                *reinterpret_cast<float4*>(b)     = *reinterpret_cast<const float4*>(&Ws[kk][tx4]);
                *reinterpret_cast<float4*>(b + 4) = *reinterpret_cast<const float4*>(&Ws[kk][64 + tx4]);
#pragma unroll
                for (int i = 0; i < 8; i++)
#pragma unroll
                    for (int j = 0; j < 8; j++) acc[i][j] += a[i] * b[j];
            }
        }
    }

    float bb[8];
#pragma unroll
    for (int j = 0; j < 8; j++)
        bb[j] = __ldg(&bl[(j < 4 ? tx4 + j : 64 + tx4 + j - 4)]);

#pragma unroll
    for (int i = 0; i < 8; i++) {
        int r = base + (i < 4 ? ty4 + i : 64 + ty4 + i - 4);
        float4 o0, o1;
        o0.x = fmaxf(acc[i][0] + bb[0], 0.f);
        o0.y = fmaxf(acc[i][1] + bb[1], 0.f);
        o0.z = fmaxf(acc[i][2] + bb[2], 0.f);
        o0.w = fmaxf(acc[i][3] + bb[3], 0.f);
        o1.x = fmaxf(acc[i][4] + bb[4], 0.f);
        o1.y = fmaxf(acc[i][5] + bb[5], 0.f);
        o1.z = fmaxf(acc[i][6] + bb[6], 0.f);
        o1.w = fmaxf(acc[i][7] + bb[7], 0.f);
        *reinterpret_cast<float4*>(&g_h[r * 128 + tx4])      = o0;
        *reinterpret_cast<float4*>(&g_h[r * 128 + 64 + tx4]) = o1;
    }
}

// ---------------- top-k pool (one block of 512 per graph) ----------------
__global__ __launch_bounds__(512) void k_pool(const float* __restrict__ pw, int k) {
    int g = blockIdx.x;
    int tid = threadIdx.x;

    __shared__ float w[128];
    __shared__ float scr[512];
    __shared__ float srt[512];
    __shared__ float fac[512];
    __shared__ unsigned char sel[512];
    __shared__ float inv_norm;
    __shared__ int cgt;

    if (tid < 128) w[tid] = pw[tid];
    if (tid == 0) cgt = 0;
    __syncthreads();
    if (tid == 0) {
        float s = 0.f;
        for (int i = 0; i < 128; i++) s += w[i] * w[i];
        inv_norm = 1.f / (sqrtf(s) + 1e-16f);
    }
    __syncthreads();

    // scores: warp per node
    int wid = tid >> 5, lane = tid & 31;
    for (int n = wid; n < 512; n += 16) {
        int node = g * 512 + n;
        float4 p = reinterpret_cast<const float4*>(g_h + node * 128)[lane];
        float4 ww = reinterpret_cast<const float4*>(w)[lane];
        float d = p.x * ww.x + p.y * ww.y + p.z * ww.z + p.w * ww.w;
#pragma unroll
        for (int off = 16; off > 0; off >>= 1)
            d += __shfl_xor_sync(0xffffffffu, d, off);
        if (lane == 0)
            scr[n] = g_nm[node] ? d * inv_norm : -INFINITY;
    }
    __syncthreads();
    srt[tid] = scr[tid];
    __syncthreads();

    // bitonic ascending sort of 512 values
    for (int kk = 2; kk <= 512; kk <<= 1) {
        for (int j = kk >> 1; j > 0; j >>= 1) {
            int ixj = tid ^ j;
            if (ixj > tid) {
                float a = srt[tid], b = srt[ixj];
                bool asc = ((tid & kk) == 0);
                if ((a > b) == asc) { srt[tid] = b; srt[ixj] = a; }
            }
            __syncthreads();
        }
    }
    float thr = srt[512 - k];   // k-th largest

    sel[tid] = (scr[tid] > thr) ? 1 : 0;
    if (scr[tid] > thr) atomicAdd(&cgt, 1);
    __syncthreads();
    if (tid == 0) {
        int need = k - cgt;   // handle ties like lax.top_k (lowest index first)
        for (int n = 0; n < 512 && need > 0; n++) {
            if (scr[n] == thr && !sel[n]) { sel[n] = 1; need--; }
        }
    }
    __syncthreads();

    fac[tid] = sel[tid] ? tanhf(scr[tid]) : 0.f;
    g_nm[g * 512 + tid] = sel[tid];
    __syncthreads();

    const float* hh = g_h + (size_t)g * 512 * 128;
    float* xx = g_x + (size_t)g * 512 * 128;
    for (int i = tid; i < 512 * 128; i += 512)
        xx[i] = hh[i] * fac[i >> 7];
}

// ---------------- readout: gmax & gmean over masked nodes ----------------
__global__ void k_readout(float kf) {
    int g = blockIdx.x;
    int c = threadIdx.x;   // 128
    const float* xb = g_x + (size_t)g * 512 * 128;
    const unsigned char* nmb = g_nm + g * 512;
    float mx = -INFINITY, sm = 0.f;
    for (int n = 0; n < 512; n++) {
        if (nmb[n]) {
            float v = xb[n * 128 + c];
            mx = fmaxf(mx, v);
            sm += v;
        }
    }
    g_z[g * 256 + c] += mx;
    g_z[g * 256 + 128 + c] += sm / kf;
}

// ---------------- MLP head ----------------
__global__ void k_mlp(const float* __restrict__ w1, const float* __restrict__ b1,
                      const float* __restrict__ w2, const float* __restrict__ b2,
                      const float* __restrict__ w3, const float* __restrict__ b3,
                      float* __restrict__ out)
{
    int g = blockIdx.x;
    int tid = threadIdx.x;   // 128
    __shared__ float z[256], t1[128], t2[64];
    z[tid] = g_z[g * 256 + tid];
    z[tid + 128] = g_z[g * 256 + 128 + tid];
    __syncthreads();
    {
        float s = b1[tid];
        for (int i = 0; i < 256; i++) s += z[i] * w1[tid * 256 + i];
        t1[tid] = fmaxf(s, 0.f);
    }
    __syncthreads();
    if (tid < 64) {
        float s = b2[tid];
        for (int i = 0; i < 128; i++) s += t1[i] * w2[tid * 128 + i];
        t2[tid] = fmaxf(s, 0.f);
    }
    __syncthreads();
    if (tid == 0) {
        float s = b3[0];
        for (int i = 0; i < 64; i++) s += t2[i] * w3[i];
        out[g] = 1.f / (1.f + expf(-s));
    }
}

// ---------------- launch ----------------
extern "C" void kernel_launch(void* const* d_in, const int* in_sizes, int n_in,
                              void* d_out, int out_size) {
    const float* x  = (const float*)d_in[0];
    const int*   ei = (const int*)d_in[1];
    const float* wl[3] = { (const float*)d_in[2], (const float*)d_in[6],  (const float*)d_in[10] };
    const float* bl[3] = { (const float*)d_in[3], (const float*)d_in[7],  (const float*)d_in[11] };
    const float* wr[3] = { (const float*)d_in[4], (const float*)d_in[8],  (const float*)d_in[12] };
    const float* pw[3] = { (const float*)d_in[5], (const float*)d_in[9],  (const float*)d_in[13] };
    const float* l1w = (const float*)d_in[14];
    const float* l1b = (const float*)d_in[15];
    const float* l2w = (const float*)d_in[16];
    const float* l2b = (const float*)d_in[17];
    const float* l3w = (const float*)d_in[18];
    const float* l3b = (const float*)d_in[19];
    float* out = (float*)d_out;

    const int KS[3] = { 410, 328, 263 };

    k_init<<<NN * DD / 512, 512>>>(x);
    k_zero_cnt<<<NN / 256, 256>>>();
    k_hist<<<EE / 256, 256>>>(ei + EE);          // dst row
    k_scan<<<1, 1024>>>();
    k_scatter<<<EE / 256, 256>>>(ei, ei + EE);   // src, dst

    for (int l = 0; l < 3; l++) {
        k_aggregate<<<NN / 8, 256>>>();
        k_gemm<<<NN / 128, 256>>>(wl[l], wr[l], bl[l]);
        k_pool<<<BB, 512>>>(pw[l], KS[l]);
        k_readout<<<BB, 128>>>((float)KS[l]);
    }
    k_mlp<<<BB, 128>>>(l1w, l1b, l2w, l2b, l3w, l3b, out);
}

// round 2
// speedup vs baseline: 1.2782x; 1.2782x over previous
#include <cuda_runtime.h>
#include <math.h>

#define NN   65536
#define DD   128
#define EE   524288
#define BB   128
#define NPER 512

// ---------------- scratch (device globals; no allocs allowed) ----------------
__device__ int   g_cnt[NN];
__device__ int   g_rowptr[NN + 1];
__device__ int   g_fill[NN];
__device__ int   g_csr[EE];
__device__ int   g_bsum[256];
__device__ int   g_boff[256];
__device__ float g_x[NN * DD];      // current node features (post-pool)
__device__ float g_mean[NN * DD];   // aggregated neighbor mean
__device__ float g_h[NN * DD];      // SAGE output (pre-pool)
__device__ unsigned char g_nm[NN];  // node mask
__device__ float g_z[BB * 256];     // summed readouts

// ---------------- helpers ----------------
__device__ __forceinline__ unsigned f2tf32(float x) {
    unsigned r;
    asm("cvt.rna.tf32.f32 %0, %1;" : "=r"(r) : "f"(x));
    return r;
}

__device__ __forceinline__ void mma_tf32(float* c,
    unsigned a0, unsigned a1, unsigned a2, unsigned a3,
    unsigned b0, unsigned b1)
{
    asm volatile(
        "mma.sync.aligned.m16n8k8.row.col.f32.tf32.tf32.f32 "
        "{%0,%1,%2,%3},{%4,%5,%6,%7},{%8,%9},{%0,%1,%2,%3};"
        : "+f"(c[0]), "+f"(c[1]), "+f"(c[2]), "+f"(c[3])
        : "r"(a0), "r"(a1), "r"(a2), "r"(a3), "r"(b0), "r"(b1));
}

// ---------------- init: copy x, mask=1, z=0 ----------------
__global__ void k_init(const float* __restrict__ x) {
    int idx = blockIdx.x * blockDim.x + threadIdx.x;   // exactly N*D threads
    g_x[idx] = x[idx];
    if (idx < NN) g_nm[idx] = 1;
    if (idx < BB * 256) g_z[idx] = 0.f;
}

__global__ void k_zero_cnt() {
    int i = blockIdx.x * blockDim.x + threadIdx.x;     // exactly N threads
    g_cnt[i] = 0;
}

__global__ void k_hist(const int* __restrict__ dst) {
    int e = blockIdx.x * blockDim.x + threadIdx.x;     // exactly E threads
    atomicAdd(&g_cnt[dst[e]], 1);
}

// ---------------- hierarchical scan (3 kernels) ----------------
__global__ void k_scan1() {
    __shared__ int sh[256];
    int b = blockIdx.x, t = threadIdx.x;
    int i = b * 256 + t;
    int c = g_cnt[i];
    sh[t] = c;
    __syncthreads();
#pragma unroll
    for (int off = 1; off < 256; off <<= 1) {
        int v = (t >= off) ? sh[t - off] : 0;
        __syncthreads();
        sh[t] += v;
        __syncthreads();
    }
    g_rowptr[i] = sh[t] - c;   // block-local exclusive
    if (t == 255) g_bsum[b] = sh[t];
}

__global__ void k_scan2() {
    __shared__ int sh[256];
    int t = threadIdx.x;
    int c = g_bsum[t];
    sh[t] = c;
    __syncthreads();
#pragma unroll
    for (int off = 1; off < 256; off <<= 1) {
        int v = (t >= off) ? sh[t - off] : 0;
        __syncthreads();
        sh[t] += v;
        __syncthreads();
    }
    g_boff[t] = sh[t] - c;     // exclusive block offsets
}

__global__ void k_scan3() {
    int b = blockIdx.x, t = threadIdx.x;
    int i = b * 256 + t;
    int v = g_rowptr[i] + g_boff[b];
    g_rowptr[i] = v;
    g_fill[i] = v;
    if (i == 0) g_rowptr[NN] = EE;
}

__global__ void k_scatter(const int* __restrict__ src, const int* __restrict__ dst) {
    int e = blockIdx.x * blockDim.x + threadIdx.x;     // exactly E threads
    int p = atomicAdd(&g_fill[dst[e]], 1);
    g_csr[p] = src[e];
}

// ---------------- neighbor mean: one warp per dst node ----------------
__global__ void k_aggregate() {
    int node = blockIdx.x * 8 + (threadIdx.x >> 5);
    int lane = threadIdx.x & 31;
    float4 acc = make_float4(0.f, 0.f, 0.f, 0.f);
    float4* Mout = reinterpret_cast<float4*>(g_mean);
    if (!g_nm[node]) { Mout[node * 32 + lane] = acc; return; }
    int r0 = g_rowptr[node], r1 = g_rowptr[node + 1];
    const float4* X = reinterpret_cast<const float4*>(g_x);
    int deg = 0;
    for (int e = r0; e < r1; e++) {
        int s = g_csr[e];
        if (g_nm[s]) {
            float4 v = X[s * 32 + lane];
            acc.x += v.x; acc.y += v.y; acc.z += v.z; acc.w += v.w;
            deg++;
        }
    }
    float inv = 1.f / (float)(deg > 1 ? deg : 1);
    acc.x *= inv; acc.y *= inv; acc.z *= inv; acc.w *= inv;
    Mout[node * 32 + lane] = acc;
}

// ---------------- fused SAGE GEMM via 3xTF32 tensor cores ----------------
// h = relu([mean|x] @ [wl|wr]^T + bl), 128x128 tile per block, K=256
// 256 threads = 8 warps in 4(M) x 2(N); each warp: m32 x n64
__global__ __launch_bounds__(256) void k_gemm(
    const float* __restrict__ wl, const float* __restrict__ wr,
    const float* __restrict__ bl)
{
    __shared__ float Ah[128][20];
    __shared__ float Al[128][20];
    __shared__ float Wh[128][20];
    __shared__ float Wlo[128][20];

    int t = threadIdx.x;
    int lane = t & 31;
    int g4 = lane >> 2;     // 0..7
    int q4 = lane & 3;      // 0..3
    int warp = t >> 5;
    int wm = warp >> 1;     // 0..3
    int wn = warp & 1;      // 0..1
    int base = blockIdx.x * 128;

    float acc[2][8][4];
#pragma unroll
    for (int mt = 0; mt < 2; mt++)
#pragma unroll
        for (int nt = 0; nt < 8; nt++)
#pragma unroll
            for (int i = 0; i < 4; i++) acc[mt][nt][i] = 0.f;

    for (int kc = 0; kc < 256; kc += 16) {
        const float* Asrc = (kc < 128) ? (g_mean + (size_t)base * 128 + kc)
                                       : (g_x    + (size_t)base * 128 + (kc - 128));
        const float* Wsrc = (kc < 128) ? (wl + kc) : (wr + (kc - 128));
        __syncthreads();
#pragma unroll
        for (int j = 0; j < 8; j++) {
            int idx = t + j * 256;
            int row = idx >> 4, k = idx & 15;
            float va = Asrc[row * 128 + k];
            float fha = __uint_as_float(f2tf32(va));
            Ah[row][k] = fha;
            Al[row][k] = __uint_as_float(f2tf32(va - fha));
            float vw = Wsrc[row * 128 + k];
            float fhw = __uint_as_float(f2tf32(vw));
            Wh[row][k]  = fhw;
            Wlo[row][k] = __uint_as_float(f2tf32(vw - fhw));
        }
        __syncthreads();
#pragma unroll
        for (int ks = 0; ks < 2; ks++) {
            int kb = ks * 8;
            unsigned aH[2][4], aL[2][4];
#pragma unroll
            for (int mt = 0; mt < 2; mt++) {
                int r = wm * 32 + mt * 16 + g4;
                aH[mt][0] = __float_as_uint(Ah[r][kb + q4]);
                aH[mt][1] = __float_as_uint(Ah[r + 8][kb + q4]);
                aH[mt][2] = __float_as_uint(Ah[r][kb + q4 + 4]);
                aH[mt][3] = __float_as_uint(Ah[r + 8][kb + q4 + 4]);
                aL[mt][0] = __float_as_uint(Al[r][kb + q4]);
                aL[mt][1] = __float_as_uint(Al[r + 8][kb + q4]);
                aL[mt][2] = __float_as_uint(Al[r][kb + q4 + 4]);
                aL[mt][3] = __float_as_uint(Al[r + 8][kb + q4 + 4]);
            }
#pragma unroll
            for (int nt = 0; nt < 8; nt++) {
                int cn = wn * 64 + nt * 8 + g4;
                unsigned b0h = __float_as_uint(Wh[cn][kb + q4]);
                unsigned b1h = __float_as_uint(Wh[cn][kb + q4 + 4]);
                unsigned b0l = __float_as_uint(Wlo[cn][kb + q4]);
                unsigned b1l = __float_as_uint(Wlo[cn][kb + q4 + 4]);
#pragma unroll
                for (int mt = 0; mt < 2; mt++) {
                    mma_tf32(acc[mt][nt], aH[mt][0], aH[mt][1], aH[mt][2], aH[mt][3], b0h, b1h);
                    mma_tf32(acc[mt][nt], aH[mt][0], aH[mt][1], aH[mt][2], aH[mt][3], b0l, b1l);
                    mma_tf32(acc[mt][nt], aL[mt][0], aL[mt][1], aL[mt][2], aL[mt][3], b0h, b1h);
                }
            }
        }
    }

    // epilogue: + bias, relu, store
#pragma unroll
    for (int nt = 0; nt < 8; nt++) {
        int col = wn * 64 + nt * 8 + q4 * 2;
        float bb0 = __ldg(bl + col);
        float bb1 = __ldg(bl + col + 1);
#pragma unroll
        for (int mt = 0; mt < 2; mt++) {
            int r = base + wm * 32 + mt * 16 + g4;
            float2 o;
            o.x = fmaxf(acc[mt][nt][0] + bb0, 0.f);
            o.y = fmaxf(acc[mt][nt][1] + bb1, 0.f);
            *reinterpret_cast<float2*>(&g_h[(size_t)r * 128 + col]) = o;
            o.x = fmaxf(acc[mt][nt][2] + bb0, 0.f);
            o.y = fmaxf(acc[mt][nt][3] + bb1, 0.f);
            *reinterpret_cast<float2*>(&g_h[(size_t)(r + 8) * 128 + col]) = o;
        }
    }
}

// ---------------- top-k pool + fused readout (one block of 512 per graph) ---
__global__ __launch_bounds__(512) void k_pool(const float* __restrict__ pw, int k, float kf) {
    int g = blockIdx.x;
    int tid = threadIdx.x;

    __shared__ float w[128];
    __shared__ float scr[512];
    __shared__ float srt[512];
    __shared__ float fac[512];
    __shared__ unsigned char sel[512];
    __shared__ float smx[4][128];
    __shared__ float ssm[4][128];
    __shared__ float inv_norm;
    __shared__ int cgt;

    if (tid < 128) w[tid] = pw[tid];
    if (tid == 0) cgt = 0;
    __syncthreads();
    if (tid == 0) {
        float s = 0.f;
        for (int i = 0; i < 128; i++) s += w[i] * w[i];
        inv_norm = 1.f / (sqrtf(s) + 1e-16f);
    }
    __syncthreads();

    // scores: warp per node
    int wid = tid >> 5, lane = tid & 31;
    for (int n = wid; n < 512; n += 16) {
        int node = g * 512 + n;
        float4 p = reinterpret_cast<const float4*>(g_h + (size_t)node * 128)[lane];
        float4 ww = reinterpret_cast<const float4*>(w)[lane];
        float d = p.x * ww.x + p.y * ww.y + p.z * ww.z + p.w * ww.w;
#pragma unroll
        for (int off = 16; off > 0; off >>= 1)
            d += __shfl_xor_sync(0xffffffffu, d, off);
        if (lane == 0)
            scr[n] = g_nm[node] ? d * inv_norm : -INFINITY;
    }
    __syncthreads();
    srt[tid] = scr[tid];
    __syncthreads();

    // bitonic ascending sort of 512 values
    for (int kk = 2; kk <= 512; kk <<= 1) {
        for (int j = kk >> 1; j > 0; j >>= 1) {
            int ixj = tid ^ j;
            if (ixj > tid) {
                float a = srt[tid], b = srt[ixj];
                bool asc = ((tid & kk) == 0);
                if ((a > b) == asc) { srt[tid] = b; srt[ixj] = a; }
            }
            __syncthreads();
        }
    }
    float thr = srt[512 - k];   // k-th largest

    sel[tid] = (scr[tid] > thr) ? 1 : 0;
    if (scr[tid] > thr) atomicAdd(&cgt, 1);
    __syncthreads();
    if (tid == 0) {
        int need = k - cgt;   // ties like lax.top_k (lowest index first)
        for (int n = 0; n < 512 && need > 0; n++) {
            if (scr[n] == thr && !sel[n]) { sel[n] = 1; need--; }
        }
    }
    __syncthreads();

    fac[tid] = sel[tid] ? tanhf(scr[tid]) : 0.f;
    g_nm[g * 512 + tid] = sel[tid];
    __syncthreads();

    // fused transform + readout
    int c = tid & 127;
    int q = tid >> 7;   // 0..3
    const float* hh = g_h + (size_t)g * 512 * 128;
    float* xx = g_x + (size_t)g * 512 * 128;
    float mx = -INFINITY, sm = 0.f;
    for (int n = q; n < 512; n += 4) {
        float v = hh[n * 128 + c] * fac[n];
        xx[n * 128 + c] = v;
        if (sel[n]) { mx = fmaxf(mx, v); sm += v; }
    }
    smx[q][c] = mx;
    ssm[q][c] = sm;
    __syncthreads();
    if (tid < 128) {
        float m = fmaxf(fmaxf(smx[0][tid], smx[1][tid]), fmaxf(smx[2][tid], smx[3][tid]));
        float s = ssm[0][tid] + ssm[1][tid] + ssm[2][tid] + ssm[3][tid];
        g_z[g * 256 + tid] += m;
        g_z[g * 256 + 128 + tid] += s / kf;
    }
}

// ---------------- MLP head ----------------
__global__ void k_mlp(const float* __restrict__ w1, const float* __restrict__ b1,
                      const float* __restrict__ w2, const float* __restrict__ b2,
                      const float* __restrict__ w3, const float* __restrict__ b3,
                      float* __restrict__ out)
{
    int g = blockIdx.x;
    int tid = threadIdx.x;   // 128
    __shared__ float z[256], t1[128], t2[64];
    z[tid] = g_z[g * 256 + tid];
    z[tid + 128] = g_z[g * 256 + 128 + tid];
    __syncthreads();
    {
        float s = b1[tid];
        for (int i = 0; i < 256; i++) s += z[i] * w1[tid * 256 + i];
        t1[tid] = fmaxf(s, 0.f);
    }
    __syncthreads();
    if (tid < 64) {
        float s = b2[tid];
        for (int i = 0; i < 128; i++) s += t1[i] * w2[tid * 128 + i];
        t2[tid] = fmaxf(s, 0.f);
    }
    __syncthreads();
    if (tid == 0) {
        float s = b3[0];
        for (int i = 0; i < 64; i++) s += t2[i] * w3[i];
        out[g] = 1.f / (1.f + expf(-s));
    }
}

// ---------------- launch ----------------
extern "C" void kernel_launch(void* const* d_in, const int* in_sizes, int n_in,
                              void* d_out, int out_size) {
    const float* x  = (const float*)d_in[0];
    const int*   ei = (const int*)d_in[1];
    const float* wl[3] = { (const float*)d_in[2], (const float*)d_in[6],  (const float*)d_in[10] };
    const float* bl[3] = { (const float*)d_in[3], (const float*)d_in[7],  (const float*)d_in[11] };
    const float* wr[3] = { (const float*)d_in[4], (const float*)d_in[8],  (const float*)d_in[12] };
    const float* pw[3] = { (const float*)d_in[5], (const float*)d_in[9],  (const float*)d_in[13] };
    const float* l1w = (const float*)d_in[14];
    const float* l1b = (const float*)d_in[15];
    const float* l2w = (const float*)d_in[16];
    const float* l2b = (const float*)d_in[17];
    const float* l3w = (const float*)d_in[18];
    const float* l3b = (const float*)d_in[19];
    float* out = (float*)d_out;

    const int KS[3] = { 410, 328, 263 };

    k_init<<<NN * DD / 512, 512>>>(x);
    k_zero_cnt<<<NN / 256, 256>>>();
    k_hist<<<EE / 256, 256>>>(ei + EE);          // dst row
    k_scan1<<<256, 256>>>();
    k_scan2<<<1, 256>>>();
    k_scan3<<<256, 256>>>();
    k_scatter<<<EE / 256, 256>>>(ei, ei + EE);   // src, dst

    for (int l = 0; l < 3; l++) {
        k_aggregate<<<NN / 8, 256>>>();
        k_gemm<<<NN / 128, 256>>>(wl[l], wr[l], bl[l]);
        k_pool<<<BB, 512>>>(pw[l], KS[l], (float)KS[l]);
    }
    k_mlp<<<BB, 128>>>(l1w, l1b, l2w, l2b, l3w, l3b, out);
}

// round 4
// speedup vs baseline: 1.6443x; 1.2864x over previous
#include <cuda_runtime.h>
#include <math.h>
#include <cstdint>

#define NN   65536
#define DD   128
#define EE   524288
#define BB   128
#define NPER 512

// ---------------- scratch (device globals; no allocs allowed) ----------------
__device__ int   g_cnt[NN];
__device__ int   g_rowptr[NN + 1];
__device__ int   g_fill[NN];
__device__ int   g_csr[EE];
__device__ int   g_bsum[256];
__device__ int   g_boff[256];
__device__ float g_x[NN * DD];      // current node features (post-pool)
__device__ float g_mean[NN * DD];   // aggregated neighbor mean
__device__ float g_h[NN * DD];      // SAGE output (pre-pool)
__device__ unsigned char g_nm[NN];  // node mask
__device__ float g_z[BB * 256];     // summed readouts

// ---------------- helpers ----------------
// pack two floats to bf16x2 (v0 -> low half, v1 -> high half)
__device__ __forceinline__ uint32_t pack_bf16x2(float v0, float v1) {
    uint32_t r;
    asm("cvt.rn.bf16x2.f32 %0, %1, %2;" : "=r"(r) : "f"(v1), "f"(v0));
    return r;
}

__device__ __forceinline__ void mma_bf16(float* c,
    uint32_t a0, uint32_t a1, uint32_t a2, uint32_t a3,
    uint32_t b0, uint32_t b1)
{
    asm volatile(
        "mma.sync.aligned.m16n8k16.row.col.f32.bf16.bf16.f32 "
        "{%0,%1,%2,%3},{%4,%5,%6,%7},{%8,%9},{%0,%1,%2,%3};"
        : "+f"(c[0]), "+f"(c[1]), "+f"(c[2]), "+f"(c[3])
        : "r"(a0), "r"(a1), "r"(a2), "r"(a3), "r"(b0), "r"(b1));
}

// split one float4 into hi/lo bf16x2 pairs
__device__ __forceinline__ void split4(float4 v, uint32_t* h, uint32_t* l) {
    h[0] = pack_bf16x2(v.x, v.y);
    float f0 = __uint_as_float(h[0] << 16);
    float f1 = __uint_as_float(h[0] & 0xFFFF0000u);
    l[0] = pack_bf16x2(v.x - f0, v.y - f1);
    h[1] = pack_bf16x2(v.z, v.w);
    float f2 = __uint_as_float(h[1] << 16);
    float f3 = __uint_as_float(h[1] & 0xFFFF0000u);
    l[1] = pack_bf16x2(v.z - f2, v.w - f3);
}

// ---------------- init: copy x, mask=1, z=0, cnt=0 ----------------
__global__ void k_init(const float* __restrict__ x) {
    int idx = blockIdx.x * blockDim.x + threadIdx.x;   // exactly N*D threads
    g_x[idx] = x[idx];
    if (idx < NN) { g_nm[idx] = 1; g_cnt[idx] = 0; }
    if (idx < BB * 256) g_z[idx] = 0.f;
}

__global__ void k_hist(const int* __restrict__ dst) {
    int e = blockIdx.x * blockDim.x + threadIdx.x;     // exactly E threads
    atomicAdd(&g_cnt[dst[e]], 1);
}

// ---------------- hierarchical scan (3 kernels) ----------------
__global__ void k_scan1() {
    __shared__ int sh[256];
    int b = blockIdx.x, t = threadIdx.x;
    int i = b * 256 + t;
    int c = g_cnt[i];
    sh[t] = c;
    __syncthreads();
#pragma unroll
    for (int off = 1; off < 256; off <<= 1) {
        int v = (t >= off) ? sh[t - off] : 0;
        __syncthreads();
        sh[t] += v;
        __syncthreads();
    }
    g_rowptr[i] = sh[t] - c;
    if (t == 255) g_bsum[b] = sh[t];
}

__global__ void k_scan2() {
    __shared__ int sh[256];
    int t = threadIdx.x;
    int c = g_bsum[t];
    sh[t] = c;
    __syncthreads();
#pragma unroll
    for (int off = 1; off < 256; off <<= 1) {
        int v = (t >= off) ? sh[t - off] : 0;
        __syncthreads();
        sh[t] += v;
        __syncthreads();
    }
    g_boff[t] = sh[t] - c;
}

__global__ void k_scan3() {
    int b = blockIdx.x, t = threadIdx.x;
    int i = b * 256 + t;
    int v = g_rowptr[i] + g_boff[b];
    g_rowptr[i] = v;
    g_fill[i] = v;
    if (i == 0) g_rowptr[NN] = EE;
}

__global__ void k_scatter(const int* __restrict__ src, const int* __restrict__ dst) {
    int e = blockIdx.x * blockDim.x + threadIdx.x;
    int p = atomicAdd(&g_fill[dst[e]], 1);
    g_csr[p] = src[e];
}

// ---------------- neighbor mean: one warp per dst node ----------------
__global__ void k_aggregate() {
    int node = blockIdx.x * 8 + (threadIdx.x >> 5);
    int lane = threadIdx.x & 31;
    float4 acc = make_float4(0.f, 0.f, 0.f, 0.f);
    float4* Mout = reinterpret_cast<float4*>(g_mean);
    if (!g_nm[node]) { Mout[node * 32 + lane] = acc; return; }
    int r0 = g_rowptr[node], r1 = g_rowptr[node + 1];
    const float4* X = reinterpret_cast<const float4*>(g_x);
    int deg = 0;
    for (int e = r0; e < r1; e++) {
        int s = g_csr[e];
        if (g_nm[s]) {
            float4 v = X[s * 32 + lane];
            acc.x += v.x; acc.y += v.y; acc.z += v.z; acc.w += v.w;
            deg++;
        }
    }
    float inv = 1.f / (float)(deg > 1 ? deg : 1);
    acc.x *= inv; acc.y *= inv; acc.z *= inv; acc.w *= inv;
    Mout[node * 32 + lane] = acc;
}

// ---------------- fused SAGE GEMM via 3xBF16 mma.sync m16n8k16 --------------
// h = relu([mean|x] @ [wl|wr]^T + bl), 128x128 tile per block, K=256 in 8
// chunks of 32. 256 threads = 8 warps, 4(M) x 2(N), warp tile m32 x n64.
__global__ __launch_bounds__(256) void k_gemm(
    const float* __restrict__ wl, const float* __restrict__ wr,
    const float* __restrict__ bl)
{
    __shared__ uint32_t Ah[128][18];
    __shared__ uint32_t Al[128][18];
    __shared__ uint32_t Wh[128][18];
    __shared__ uint32_t Wl[128][18];
    __shared__ float sbias[128];

    int t = threadIdx.x;
    int lane = t & 31;
    int g = lane >> 2;      // 0..7
    int tq = lane & 3;      // 0..3
    int warp = t >> 5;
    int wm = warp >> 1;     // 0..3
    int wn = warp & 1;      // 0..1
    int base = blockIdx.x * 128;

    if (t < 128) sbias[t] = bl[t];

    float acc[2][8][4];
#pragma unroll
    for (int mt = 0; mt < 2; mt++)
#pragma unroll
        for (int nt = 0; nt < 8; nt++)
#pragma unroll
            for (int i = 0; i < 4; i++) acc[mt][nt][i] = 0.f;

    for (int c = 0; c < 8; c++) {
        int kc = c * 32;
        const float* Asrc = (kc < 128) ? (g_mean + (size_t)base * 128 + kc)
                                       : (g_x    + (size_t)base * 128 + (kc - 128));
        const float* Wsrc = (kc < 128) ? (wl + kc) : (wr + (kc - 128));
        __syncthreads();
#pragma unroll
        for (int j = 0; j < 4; j++) {
            int idx = t + j * 256;          // 0..1023
            int row = idx >> 3;             // 0..127
            int q = idx & 7;                // float4 index within 32 k-els
            uint32_t h[2], l[2];
            float4 va = *reinterpret_cast<const float4*>(Asrc + (size_t)row * 128 + q * 4);
            split4(va, h, l);
            Ah[row][q * 2] = h[0]; Ah[row][q * 2 + 1] = h[1];
            Al[row][q * 2] = l[0]; Al[row][q * 2 + 1] = l[1];
            float4 vw = *reinterpret_cast<const float4*>(Wsrc + (size_t)row * 128 + q * 4);
            split4(vw, h, l);
            Wh[row][q * 2] = h[0]; Wh[row][q * 2 + 1] = h[1];
            Wl[row][q * 2] = l[0]; Wl[row][q * 2 + 1] = l[1];
        }
        __syncthreads();
#pragma unroll
        for (int ks = 0; ks < 2; ks++) {
            int cb = ks * 8;                // packed-u32 column base (k16)
            uint32_t aH[2][4], aL[2][4];
#pragma unroll
            for (int mt = 0; mt < 2; mt++) {
                int r = wm * 32 + mt * 16 + g;
                aH[mt][0] = Ah[r][cb + tq];
                aH[mt][1] = Ah[r + 8][cb + tq];
                aH[mt][2] = Ah[r][cb + 4 + tq];
                aH[mt][3] = Ah[r + 8][cb + 4 + tq];
                aL[mt][0] = Al[r][cb + tq];
                aL[mt][1] = Al[r + 8][cb + tq];
                aL[mt][2] = Al[r][cb + 4 + tq];
                aL[mt][3] = Al[r + 8][cb + 4 + tq];
            }
#pragma unroll
            for (int nt = 0; nt < 8; nt++) {
                int n = wn * 64 + nt * 8 + g;
                uint32_t bh0 = Wh[n][cb + tq];
                uint32_t bh1 = Wh[n][cb + 4 + tq];
                uint32_t bl0 = Wl[n][cb + tq];
                uint32_t bl1 = Wl[n][cb + 4 + tq];
#pragma unroll
                for (int mt = 0; mt < 2; mt++) {
                    mma_bf16(acc[mt][nt], aH[mt][0], aH[mt][1], aH[mt][2], aH[mt][3], bh0, bh1);
                    mma_bf16(acc[mt][nt], aH[mt][0], aH[mt][1], aH[mt][2], aH[mt][3], bl0, bl1);
                    mma_bf16(acc[mt][nt], aL[mt][0], aL[mt][1], aL[mt][2], aL[mt][3], bh0, bh1);
                }
            }
        }
    }

    // epilogue: + bias, relu, store
#pragma unroll
    for (int nt = 0; nt < 8; nt++) {
        int col = wn * 64 + nt * 8 + tq * 2;
        float bb0 = sbias[col];
        float bb1 = sbias[col + 1];
#pragma unroll
        for (int mt = 0; mt < 2; mt++) {
            int r = base + wm * 32 + mt * 16 + g;
            float2 o;
            o.x = fmaxf(acc[mt][nt][0] + bb0, 0.f);
            o.y = fmaxf(acc[mt][nt][1] + bb1, 0.f);
            *reinterpret_cast<float2*>(&g_h[(size_t)r * 128 + col]) = o;
            o.x = fmaxf(acc[mt][nt][2] + bb0, 0.f);
            o.y = fmaxf(acc[mt][nt][3] + bb1, 0.f);
            *reinterpret_cast<float2*>(&g_h[(size_t)(r + 8) * 128 + col]) = o;
        }
    }
}

// ---------------- top-k pool + fused readout (one block of 512 per graph) ---
__global__ __launch_bounds__(512) void k_pool(const float* __restrict__ pw, int k, float kf) {
    int g = blockIdx.x;
    int tid = threadIdx.x;

    __shared__ float w[128];
    __shared__ float scr[512];
    __shared__ float srt[512];
    __shared__ float fac[512];
    __shared__ unsigned char sel[512];
    __shared__ float smx[4][128];
    __shared__ float ssm[4][128];
    __shared__ float inv_norm;
    __shared__ int cgt;

    if (tid < 128) w[tid] = pw[tid];
    if (tid == 0) cgt = 0;
    __syncthreads();
    if (tid == 0) {
        float s = 0.f;
        for (int i = 0; i < 128; i++) s += w[i] * w[i];
        inv_norm = 1.f / (sqrtf(s) + 1e-16f);
    }
    __syncthreads();

    int wid = tid >> 5, lane = tid & 31;
    for (int n = wid; n < 512; n += 16) {
        int node = g * 512 + n;
        float4 p = reinterpret_cast<const float4*>(g_h + (size_t)node * 128)[lane];
        float4 ww = reinterpret_cast<const float4*>(w)[lane];
        float d = p.x * ww.x + p.y * ww.y + p.z * ww.z + p.w * ww.w;
#pragma unroll
        for (int off = 16; off > 0; off >>= 1)
            d += __shfl_xor_sync(0xffffffffu, d, off);
        if (lane == 0)
            scr[n] = g_nm[node] ? d * inv_norm : -INFINITY;
    }
    __syncthreads();
    srt[tid] = scr[tid];
    __syncthreads();

    for (int kk = 2; kk <= 512; kk <<= 1) {
        for (int j = kk >> 1; j > 0; j >>= 1) {
            int ixj = tid ^ j;
            if (ixj > tid) {
                float a = srt[tid], b = srt[ixj];
                bool asc = ((tid & kk) == 0);
                if ((a > b) == asc) { srt[tid] = b; srt[ixj] = a; }
            }
            __syncthreads();
        }
    }
    float thr = srt[512 - k];

    sel[tid] = (scr[tid] > thr) ? 1 : 0;
    if (scr[tid] > thr) atomicAdd(&cgt, 1);
    __syncthreads();
    if (tid == 0) {
        int need = k - cgt;
        for (int n = 0; n < 512 && need > 0; n++) {
            if (scr[n] == thr && !sel[n]) { sel[n] = 1; need--; }
        }
    }
    __syncthreads();

    fac[tid] = sel[tid] ? tanhf(scr[tid]) : 0.f;
    g_nm[g * 512 + tid] = sel[tid];
    __syncthreads();

    int c = tid & 127;
    int q = tid >> 7;
    const float* hh = g_h + (size_t)g * 512 * 128;
    float* xx = g_x + (size_t)g * 512 * 128;
    float mx = -INFINITY, sm = 0.f;
    for (int n = q; n < 512; n += 4) {
        float v = hh[n * 128 + c] * fac[n];
        xx[n * 128 + c] = v;
        if (sel[n]) { mx = fmaxf(mx, v); sm += v; }
    }
    smx[q][c] = mx;
    ssm[q][c] = sm;
    __syncthreads();
    if (tid < 128) {
        float m = fmaxf(fmaxf(smx[0][tid], smx[1][tid]), fmaxf(smx[2][tid], smx[3][tid]));
        float s = ssm[0][tid] + ssm[1][tid] + ssm[2][tid] + ssm[3][tid];
        g_z[g * 256 + tid] += m;
        g_z[g * 256 + 128 + tid] += s / kf;
    }
}

// ---------------- MLP head ----------------
__global__ void k_mlp(const float* __restrict__ w1, const float* __restrict__ b1,
                      const float* __restrict__ w2, const float* __restrict__ b2,
                      const float* __restrict__ w3, const float* __restrict__ b3,
                      float* __restrict__ out)
{
    int g = blockIdx.x;
    int tid = threadIdx.x;
    __shared__ float z[256], t1[128], t2[64];
    z[tid] = g_z[g * 256 + tid];
    z[tid + 128] = g_z[g * 256 + 128 + tid];
    __syncthreads();
    {
        float s = b1[tid];
        for (int i = 0; i < 256; i++) s += z[i] * w1[tid * 256 + i];
        t1[tid] = fmaxf(s, 0.f);
    }
    __syncthreads();
    if (tid < 64) {
        float s = b2[tid];
        for (int i = 0; i < 128; i++) s += t1[i] * w2[tid * 128 + i];
        t2[tid] = fmaxf(s, 0.f);
    }
    __syncthreads();
    if (tid == 0) {
        float s = b3[0];
        for (int i = 0; i < 64; i++) s += t2[i] * w3[i];
        out[g] = 1.f / (1.f + expf(-s));
    }
}

// ---------------- launch ----------------
extern "C" void kernel_launch(void* const* d_in, const int* in_sizes, int n_in,
                              void* d_out, int out_size) {
    const float* x  = (const float*)d_in[0];
    const int*   ei = (const int*)d_in[1];
    const float* wl[3] = { (const float*)d_in[2], (const float*)d_in[6],  (const float*)d_in[10] };
    const float* bl[3] = { (const float*)d_in[3], (const float*)d_in[7],  (const float*)d_in[11] };
    const float* wr[3] = { (const float*)d_in[4], (const float*)d_in[8],  (const float*)d_in[12] };
    const float* pw[3] = { (const float*)d_in[5], (const float*)d_in[9],  (const float*)d_in[13] };
    const float* l1w = (const float*)d_in[14];
    const float* l1b = (const float*)d_in[15];
    const float* l2w = (const float*)d_in[16];
    const float* l2b = (const float*)d_in[17];
    const float* l3w = (const float*)d_in[18];
    const float* l3b = (const float*)d_in[19];
    float* out = (float*)d_out;

    const int KS[3] = { 410, 328, 263 };

    k_init<<<NN * DD / 512, 512>>>(x);
    k_hist<<<EE / 256, 256>>>(ei + EE);
    k_scan1<<<256, 256>>>();
    k_scan2<<<1, 256>>>();
    k_scan3<<<256, 256>>>();
    k_scatter<<<EE / 256, 256>>>(ei, ei + EE);

    for (int l = 0; l < 3; l++) {
        k_aggregate<<<NN / 8, 256>>>();
        k_gemm<<<NN / 128, 256>>>(wl[l], wr[l], bl[l]);
        k_pool<<<BB, 512>>>(pw[l], KS[l], (float)KS[l]);
    }
    k_mlp<<<BB, 128>>>(l1w, l1b, l2w, l2b, l3w, l3b, out);
}

// round 5
// speedup vs baseline: 1.9356x; 1.1771x over previous
#include <cuda_runtime.h>
#include <math.h>
#include <cstdint>

#define NN   65536
#define DD   128
#define EE   524288
#define BB   128
#define NPER 512

// ---------------- scratch (device globals; no allocs allowed) ----------------
__device__ int   g_cnt[NN];
__device__ int   g_rowptr[NN + 1];
__device__ int   g_fill[NN];
__device__ int   g_csr[EE];
__device__ int   g_bsum[256];
__device__ int   g_boff[256];
__device__ uint32_t g_xH[NN * 64];   // x as packed bf16x2, hi part
__device__ uint32_t g_xL[NN * 64];   // x lo correction
__device__ uint32_t g_mH[NN * 64];   // mean hi
__device__ uint32_t g_mL[NN * 64];   // mean lo
__device__ uint32_t g_wH[6][128 * 64]; // weights hi: [layer*2 + (0=wl,1=wr)]
__device__ uint32_t g_wL[6][128 * 64]; // weights lo
__device__ float g_h[NN * DD];      // SAGE output (pre-pool), fp32
__device__ unsigned char g_nm[NN];  // node mask
__device__ float g_z[BB * 256];     // summed readouts

// ---------------- helpers ----------------
__device__ __forceinline__ uint32_t pack_bf16x2(float v0, float v1) {
    uint32_t r;
    asm("cvt.rn.bf16x2.f32 %0, %1, %2;" : "=r"(r) : "f"(v1), "f"(v0));
    return r;
}
__device__ __forceinline__ float bf_lo(uint32_t u) { return __uint_as_float(u << 16); }
__device__ __forceinline__ float bf_hi(uint32_t u) { return __uint_as_float(u & 0xFFFF0000u); }

__device__ __forceinline__ void mma_bf16(float* c,
    uint32_t a0, uint32_t a1, uint32_t a2, uint32_t a3,
    uint32_t b0, uint32_t b1)
{
    asm volatile(
        "mma.sync.aligned.m16n8k16.row.col.f32.bf16.bf16.f32 "
        "{%0,%1,%2,%3},{%4,%5,%6,%7},{%8,%9},{%0,%1,%2,%3};"
        : "+f"(c[0]), "+f"(c[1]), "+f"(c[2]), "+f"(c[3])
        : "r"(a0), "r"(a1), "r"(a2), "r"(a3), "r"(b0), "r"(b1));
}

__device__ __forceinline__ uint32_t smem_u32(const void* p) {
    uint32_t a;
    asm("{ .reg .u64 t; cvta.to.shared.u64 t, %1; cvt.u32.u64 %0, t; }" : "=r"(a) : "l"(p));
    return a;
}
__device__ __forceinline__ void cp16(uint32_t saddr, const void* gaddr) {
    asm volatile("cp.async.cg.shared.global [%0], [%1], 16;" :: "r"(saddr), "l"(gaddr) : "memory");
}
#define CP_COMMIT() asm volatile("cp.async.commit_group;" ::: "memory")
#define CP_WAIT1()  asm volatile("cp.async.wait_group 1;" ::: "memory")
#define CP_WAIT0()  asm volatile("cp.async.wait_group 0;" ::: "memory")

// ---------------- init: x -> hi/lo splits, mask=1, z=0, cnt=0 ----------------
__global__ void k_init(const float* __restrict__ x) {
    int i = blockIdx.x * blockDim.x + threadIdx.x;   // exactly NN*64 threads
    float2 v = reinterpret_cast<const float2*>(x)[i];
    uint32_t h = pack_bf16x2(v.x, v.y);
    uint32_t l = pack_bf16x2(v.x - bf_lo(h), v.y - bf_hi(h));
    g_xH[i] = h;
    g_xL[i] = l;
    if (i < NN) { g_nm[i] = 1; g_cnt[i] = 0; }
    if (i < BB * 256) g_z[i] = 0.f;
}

// ---------------- weight pre-split: 6 matrices of 128x128 fp32 ----------------
__global__ void k_prepw(const float* w0, const float* w1, const float* w2,
                        const float* w3, const float* w4, const float* w5) {
    const float* ws[6] = { w0, w1, w2, w3, w4, w5 };
    int m = blockIdx.y;
    int i = blockIdx.x * blockDim.x + threadIdx.x;   // 0..8191
    float2 v = reinterpret_cast<const float2*>(ws[m])[i];
    uint32_t h = pack_bf16x2(v.x, v.y);
    uint32_t l = pack_bf16x2(v.x - bf_lo(h), v.y - bf_hi(h));
    g_wH[m][i] = h;
    g_wL[m][i] = l;
}

__global__ void k_hist(const int* __restrict__ dst) {
    int e = blockIdx.x * blockDim.x + threadIdx.x;
    atomicAdd(&g_cnt[dst[e]], 1);
}

// ---------------- hierarchical scan (3 kernels) ----------------
__global__ void k_scan1() {
    __shared__ int sh[256];
    int b = blockIdx.x, t = threadIdx.x;
    int i = b * 256 + t;
    int c = g_cnt[i];
    sh[t] = c;
    __syncthreads();
#pragma unroll
    for (int off = 1; off < 256; off <<= 1) {
        int v = (t >= off) ? sh[t - off] : 0;
        __syncthreads();
        sh[t] += v;
        __syncthreads();
    }
    g_rowptr[i] = sh[t] - c;
    if (t == 255) g_bsum[b] = sh[t];
}

__global__ void k_scan2() {
    __shared__ int sh[256];
    int t = threadIdx.x;
    int c = g_bsum[t];
    sh[t] = c;
    __syncthreads();
#pragma unroll
    for (int off = 1; off < 256; off <<= 1) {
        int v = (t >= off) ? sh[t - off] : 0;
        __syncthreads();
        sh[t] += v;
        __syncthreads();
    }
    g_boff[t] = sh[t] - c;
}

__global__ void k_scan3() {
    int b = blockIdx.x, t = threadIdx.x;
    int i = b * 256 + t;
    int v = g_rowptr[i] + g_boff[b];
    g_rowptr[i] = v;
    g_fill[i] = v;
    if (i == 0) g_rowptr[NN] = EE;
}

__global__ void k_scatter(const int* __restrict__ src, const int* __restrict__ dst) {
    int e = blockIdx.x * blockDim.x + threadIdx.x;
    int p = atomicAdd(&g_fill[dst[e]], 1);
    g_csr[p] = src[e];
}

// ---------------- neighbor mean (split in/out): one warp per dst node -------
__global__ void k_aggregate() {
    int node = blockIdx.x * 8 + (threadIdx.x >> 5);
    int lane = threadIdx.x & 31;
    uint2* MH = reinterpret_cast<uint2*>(g_mH);
    uint2* ML = reinterpret_cast<uint2*>(g_mL);
    if (!g_nm[node]) {
        MH[node * 32 + lane] = make_uint2(0u, 0u);
        ML[node * 32 + lane] = make_uint2(0u, 0u);
        return;
    }
    int r0 = g_rowptr[node], r1 = g_rowptr[node + 1];
    const uint2* XH = reinterpret_cast<const uint2*>(g_xH);
    const uint2* XL = reinterpret_cast<const uint2*>(g_xL);
    float a0 = 0.f, a1 = 0.f, a2 = 0.f, a3 = 0.f;
    int deg = 0;
    for (int e = r0; e < r1; e++) {
        int s = g_csr[e];
        if (g_nm[s]) {
            uint2 h = XH[s * 32 + lane];
            uint2 l = XL[s * 32 + lane];
            a0 += bf_lo(h.x) + bf_lo(l.x);
            a1 += bf_hi(h.x) + bf_hi(l.x);
            a2 += bf_lo(h.y) + bf_lo(l.y);
            a3 += bf_hi(h.y) + bf_hi(l.y);
            deg++;
        }
    }
    float inv = 1.f / (float)(deg > 1 ? deg : 1);
    a0 *= inv; a1 *= inv; a2 *= inv; a3 *= inv;
    uint32_t h0 = pack_bf16x2(a0, a1);
    uint32_t h1 = pack_bf16x2(a2, a3);
    uint32_t l0 = pack_bf16x2(a0 - bf_lo(h0), a1 - bf_hi(h0));
    uint32_t l1 = pack_bf16x2(a2 - bf_lo(h1), a3 - bf_hi(h1));
    MH[node * 32 + lane] = make_uint2(h0, h1);
    ML[node * 32 + lane] = make_uint2(l0, l1);
}

// ---------------- 3xBF16 GEMM, cp.async double-buffered ----------------
// h = relu([mean|x] @ [wl|wr]^T + bl). 128x128 tile, K=256 in 8 chunks of 32.
// Operands already split+packed: just copy global->smem, ld fragments, MMA.
// Dynamic smem: 2 stages x 4 bufs x 128x20 u32 = 81920 bytes.
#define BUF_U32   2560          // 128*20
#define STG_U32   10240         // 4 buffers
#define SMEM_GEMM 81920

__global__ __launch_bounds__(256, 2) void k_gemm(int layer, const float* __restrict__ bl)
{
    extern __shared__ __align__(16) uint32_t dsm[];
    __shared__ float sbias[128];
    uint32_t sb0 = smem_u32(dsm);

    int t = threadIdx.x;
    int lane = t & 31;
    int g = lane >> 2;      // 0..7
    int tq = lane & 3;      // 0..3
    int warp = t >> 5;
    int wm = warp >> 1;     // 0..3
    int wn = warp & 1;      // 0..1
    int base = blockIdx.x * 128;
    size_t bofs = (size_t)base * 64;

    if (t < 128) sbias[t] = bl[t];

    // per-thread copy slots: s0=t -> row t>>2, s1=t+256 -> row 64+(t>>2), col q=(t&3)*4
    int r0 = t >> 2, q4 = (t & 3) * 4;
    int r1 = r0 + 64;

    float acc[2][8][4];
#pragma unroll
    for (int mt = 0; mt < 2; mt++)
#pragma unroll
        for (int nt = 0; nt < 8; nt++)
#pragma unroll
            for (int i = 0; i < 4; i++) acc[mt][nt][i] = 0.f;

    // issue chunk c into stage st
    auto issue = [&](int c, int st) {
        const uint32_t* aH = (c < 4 ? g_mH : g_xH) + bofs + (c & 3) * 16;
        const uint32_t* aL = (c < 4 ? g_mL : g_xL) + bofs + (c & 3) * 16;
        const uint32_t* wH = g_wH[(layer << 1) | (c >> 2)] + (c & 3) * 16;
        const uint32_t* wLp = g_wL[(layer << 1) | (c >> 2)] + (c & 3) * 16;
        uint32_t sb = sb0 + st * (STG_U32 * 4);
        cp16(sb + (r0 * 20 + q4) * 4,                 aH + (size_t)r0 * 64 + q4);
        cp16(sb + (r1 * 20 + q4) * 4,                 aH + (size_t)r1 * 64 + q4);
        cp16(sb + (BUF_U32 + r0 * 20 + q4) * 4,       aL + (size_t)r0 * 64 + q4);
        cp16(sb + (BUF_U32 + r1 * 20 + q4) * 4,       aL + (size_t)r1 * 64 + q4);
        cp16(sb + (2 * BUF_U32 + r0 * 20 + q4) * 4,   wH + (size_t)r0 * 64 + q4);
        cp16(sb + (2 * BUF_U32 + r1 * 20 + q4) * 4,   wH + (size_t)r1 * 64 + q4);
        cp16(sb + (3 * BUF_U32 + r0 * 20 + q4) * 4,   wLp + (size_t)r0 * 64 + q4);
        cp16(sb + (3 * BUF_U32 + r1 * 20 + q4) * 4,   wLp + (size_t)r1 * 64 + q4);
        CP_COMMIT();
    };

    issue(0, 0);
    for (int c = 0; c < 8; c++) {
        int st = c & 1;
        if (c < 7) { issue(c + 1, st ^ 1); CP_WAIT1(); }
        else       { CP_WAIT0(); }
        __syncthreads();

        const uint32_t* AH = dsm + st * STG_U32;
        const uint32_t* AL = AH + BUF_U32;
        const uint32_t* WH = AH + 2 * BUF_U32;
        const uint32_t* WL = AH + 3 * BUF_U32;

#pragma unroll
        for (int ks = 0; ks < 2; ks++) {
            int cb = ks * 8;
            uint32_t aH[2][4], aL[2][4];
#pragma unroll
            for (int mt = 0; mt < 2; mt++) {
                int r = wm * 32 + mt * 16 + g;
                aH[mt][0] = AH[r * 20 + cb + tq];
                aH[mt][1] = AH[(r + 8) * 20 + cb + tq];
                aH[mt][2] = AH[r * 20 + cb + 4 + tq];
                aH[mt][3] = AH[(r + 8) * 20 + cb + 4 + tq];
                aL[mt][0] = AL[r * 20 + cb + tq];
                aL[mt][1] = AL[(r + 8) * 20 + cb + tq];
                aL[mt][2] = AL[r * 20 + cb + 4 + tq];
                aL[mt][3] = AL[(r + 8) * 20 + cb + 4 + tq];
            }
#pragma unroll
            for (int nt = 0; nt < 8; nt++) {
                int n = wn * 64 + nt * 8 + g;
                uint32_t bh0 = WH[n * 20 + cb + tq];
                uint32_t bh1 = WH[n * 20 + cb + 4 + tq];
                uint32_t bl0 = WL[n * 20 + cb + tq];
                uint32_t bl1 = WL[n * 20 + cb + 4 + tq];
#pragma unroll
                for (int mt = 0; mt < 2; mt++) {
                    mma_bf16(acc[mt][nt], aH[mt][0], aH[mt][1], aH[mt][2], aH[mt][3], bh0, bh1);
                    mma_bf16(acc[mt][nt], aH[mt][0], aH[mt][1], aH[mt][2], aH[mt][3], bl0, bl1);
                    mma_bf16(acc[mt][nt], aL[mt][0], aL[mt][1], aL[mt][2], aL[mt][3], bh0, bh1);
                }
            }
        }
        __syncthreads();
    }

    // epilogue: + bias, relu, store fp32 h
#pragma unroll
    for (int nt = 0; nt < 8; nt++) {
        int col = wn * 64 + nt * 8 + tq * 2;
        float bb0 = sbias[col];
        float bb1 = sbias[col + 1];
#pragma unroll
        for (int mt = 0; mt < 2; mt++) {
            int r = base + wm * 32 + mt * 16 + g;
            float2 o;
            o.x = fmaxf(acc[mt][nt][0] + bb0, 0.f);
            o.y = fmaxf(acc[mt][nt][1] + bb1, 0.f);
            *reinterpret_cast<float2*>(&g_h[(size_t)r * 128 + col]) = o;
            o.x = fmaxf(acc[mt][nt][2] + bb0, 0.f);
            o.y = fmaxf(acc[mt][nt][3] + bb1, 0.f);
            *reinterpret_cast<float2*>(&g_h[(size_t)(r + 8) * 128 + col]) = o;
        }
    }
}

// ---------------- top-k pool + fused readout + split-x output ----------------
__global__ __launch_bounds__(512) void k_pool(const float* __restrict__ pw, int k, float kf) {
    int g = blockIdx.x;
    int tid = threadIdx.x;

    __shared__ float w[128];
    __shared__ float scr[512];
    __shared__ float srt[512];
    __shared__ float fac[512];
    __shared__ unsigned char sel[512];
    __shared__ float smx[8][128];
    __shared__ float ssm[8][128];
    __shared__ float inv_norm;
    __shared__ int cgt;

    if (tid < 128) w[tid] = pw[tid];
    if (tid == 0) cgt = 0;
    __syncthreads();
    if (tid == 0) {
        float s = 0.f;
        for (int i = 0; i < 128; i++) s += w[i] * w[i];
        inv_norm = 1.f / (sqrtf(s) + 1e-16f);
    }
    __syncthreads();

    int wid = tid >> 5, lane = tid & 31;
    for (int n = wid; n < 512; n += 16) {
        int node = g * 512 + n;
        float4 p = reinterpret_cast<const float4*>(g_h + (size_t)node * 128)[lane];
        float4 ww = reinterpret_cast<const float4*>(w)[lane];
        float d = p.x * ww.x + p.y * ww.y + p.z * ww.z + p.w * ww.w;
#pragma unroll
        for (int off = 16; off > 0; off >>= 1)
            d += __shfl_xor_sync(0xffffffffu, d, off);
        if (lane == 0)
            scr[n] = g_nm[node] ? d * inv_norm : -INFINITY;
    }
    __syncthreads();
    srt[tid] = scr[tid];
    __syncthreads();

    for (int kk = 2; kk <= 512; kk <<= 1) {
        for (int j = kk >> 1; j > 0; j >>= 1) {
            int ixj = tid ^ j;
            if (ixj > tid) {
                float a = srt[tid], b = srt[ixj];
                bool asc = ((tid & kk) == 0);
                if ((a > b) == asc) { srt[tid] = b; srt[ixj] = a; }
            }
            __syncthreads();
        }
    }
    float thr = srt[512 - k];

    sel[tid] = (scr[tid] > thr) ? 1 : 0;
    if (scr[tid] > thr) atomicAdd(&cgt, 1);
    __syncthreads();
    if (tid == 0) {
        int need = k - cgt;
        for (int n = 0; n < 512 && need > 0; n++) {
            if (scr[n] == thr && !sel[n]) { sel[n] = 1; need--; }
        }
    }
    __syncthreads();

    fac[tid] = sel[tid] ? tanhf(scr[tid]) : 0.f;
    g_nm[g * 512 + tid] = sel[tid];
    __syncthreads();

    // fused transform (writes split x) + readout; thread owns column pair 2c2,2c2+1
    int c2 = tid & 63;
    int q = tid >> 6;   // 0..7
    const float* hh = g_h + (size_t)g * 512 * 128;
    uint32_t* xh = g_xH + (size_t)g * 512 * 64;
    uint32_t* xl = g_xL + (size_t)g * 512 * 64;
    float mx0 = -INFINITY, sm0 = 0.f, mx1 = -INFINITY, sm1 = 0.f;
    for (int n = q; n < 512; n += 8) {
        float f = fac[n];
        float v0 = hh[n * 128 + 2 * c2] * f;
        float v1 = hh[n * 128 + 2 * c2 + 1] * f;
        uint32_t H = pack_bf16x2(v0, v1);
        uint32_t L = pack_bf16x2(v0 - bf_lo(H), v1 - bf_hi(H));
        xh[n * 64 + c2] = H;
        xl[n * 64 + c2] = L;
        if (sel[n]) {
            mx0 = fmaxf(mx0, v0); sm0 += v0;
            mx1 = fmaxf(mx1, v1); sm1 += v1;
        }
    }
    smx[q][2 * c2] = mx0; smx[q][2 * c2 + 1] = mx1;
    ssm[q][2 * c2] = sm0; ssm[q][2 * c2 + 1] = sm1;
    __syncthreads();
    if (tid < 128) {
        float m = smx[0][tid], s = ssm[0][tid];
#pragma unroll
        for (int i = 1; i < 8; i++) { m = fmaxf(m, smx[i][tid]); s += ssm[i][tid]; }
        g_z[g * 256 + tid] += m;
        g_z[g * 256 + 128 + tid] += s / kf;
    }
}

// ---------------- MLP head ----------------
__global__ void k_mlp(const float* __restrict__ w1, const float* __restrict__ b1,
                      const float* __restrict__ w2, const float* __restrict__ b2,
                      const float* __restrict__ w3, const float* __restrict__ b3,
                      float* __restrict__ out)
{
    int g = blockIdx.x;
    int tid = threadIdx.x;
    __shared__ float z[256], t1[128], t2[64];
    z[tid] = g_z[g * 256 + tid];
    z[tid + 128] = g_z[g * 256 + 128 + tid];
    __syncthreads();
    {
        float s = b1[tid];
        for (int i = 0; i < 256; i++) s += z[i] * w1[tid * 256 + i];
        t1[tid] = fmaxf(s, 0.f);
    }
    __syncthreads();
    if (tid < 64) {
        float s = b2[tid];
        for (int i = 0; i < 128; i++) s += t1[i] * w2[tid * 128 + i];
        t2[tid] = fmaxf(s, 0.f);
    }
    __syncthreads();
    if (tid == 0) {
        float s = b3[0];
        for (int i = 0; i < 64; i++) s += t2[i] * w3[i];
        out[g] = 1.f / (1.f + expf(-s));
    }
}

// ---------------- launch ----------------
extern "C" void kernel_launch(void* const* d_in, const int* in_sizes, int n_in,
                              void* d_out, int out_size) {
    const float* x  = (const float*)d_in[0];
    const int*   ei = (const int*)d_in[1];
    const float* wl[3] = { (const float*)d_in[2], (const float*)d_in[6],  (const float*)d_in[10] };
    const float* bl[3] = { (const float*)d_in[3], (const float*)d_in[7],  (const float*)d_in[11] };
    const float* wr[3] = { (const float*)d_in[4], (const float*)d_in[8],  (const float*)d_in[12] };
    const float* pw[3] = { (const float*)d_in[5], (const float*)d_in[9],  (const float*)d_in[13] };
    const float* l1w = (const float*)d_in[14];
    const float* l1b = (const float*)d_in[15];
    const float* l2w = (const float*)d_in[16];
    const float* l2b = (const float*)d_in[17];
    const float* l3w = (const float*)d_in[18];
    const float* l3b = (const float*)d_in[19];
    float* out = (float*)d_out;

    const int KS[3] = { 410, 328, 263 };

    cudaFuncSetAttribute(k_gemm, cudaFuncAttributeMaxDynamicSharedMemorySize, SMEM_GEMM);

    k_init<<<NN * 64 / 256, 256>>>(x);
    k_prepw<<<dim3(32, 6), 256>>>(wl[0], wr[0], wl[1], wr[1], wl[2], wr[2]);
    k_hist<<<EE / 256, 256>>>(ei + EE);
    k_scan1<<<256, 256>>>();
    k_scan2<<<1, 256>>>();
    k_scan3<<<256, 256>>>();
    k_scatter<<<EE / 256, 256>>>(ei, ei + EE);

    for (int l = 0; l < 3; l++) {
        k_aggregate<<<NN / 8, 256>>>();
        k_gemm<<<NN / 128, 256, SMEM_GEMM>>>(l, bl[l]);
        k_pool<<<BB, 512>>>(pw[l], KS[l], (float)KS[l]);
    }
    k_mlp<<<BB, 128>>>(l1w, l1b, l2w, l2b, l3w, l3b, out);
}

// round 6
// speedup vs baseline: 2.0122x; 1.0396x over previous
#include <cuda_runtime.h>
#include <math.h>
#include <cstdint>

#define NN   65536
#define DD   128
#define EE   524288
#define BB   128
#define NPER 512

// ---------------- scratch (device globals; no allocs allowed) ----------------
__device__ int   g_cnt[NN];
__device__ int   g_rowptr[NN + 1];
__device__ int   g_fill[NN];
__device__ int   g_csr[EE];
__device__ int   g_bsum[256];
__device__ int   g_boff[256];
__device__ uint32_t g_xH[NN * 64];   // x as packed bf16x2, hi part
__device__ uint32_t g_xL[NN * 64];   // x lo correction
__device__ uint32_t g_mH[NN * 64];   // mean hi
__device__ uint32_t g_mL[NN * 64];   // mean lo
__device__ uint32_t g_wH[6][128 * 64]; // weights hi: [layer*2 + (0=wl,1=wr)]
__device__ uint32_t g_wL[6][128 * 64]; // weights lo
__device__ float g_h[NN * DD];      // SAGE output (pre-pool), fp32
__device__ unsigned char g_nm[NN];  // node mask
__device__ float g_z[BB * 256];     // summed readouts

// ---------------- helpers ----------------
__device__ __forceinline__ uint32_t pack_bf16x2(float v0, float v1) {
    uint32_t r;
    asm("cvt.rn.bf16x2.f32 %0, %1, %2;" : "=r"(r) : "f"(v1), "f"(v0));
    return r;
}
__device__ __forceinline__ float bf_lo(uint32_t u) { return __uint_as_float(u << 16); }
__device__ __forceinline__ float bf_hi(uint32_t u) { return __uint_as_float(u & 0xFFFF0000u); }

__device__ __forceinline__ void mma_bf16(float* c,
    uint32_t a0, uint32_t a1, uint32_t a2, uint32_t a3,
    uint32_t b0, uint32_t b1)
{
    asm volatile(
        "mma.sync.aligned.m16n8k16.row.col.f32.bf16.bf16.f32 "
        "{%0,%1,%2,%3},{%4,%5,%6,%7},{%8,%9},{%0,%1,%2,%3};"
        : "+f"(c[0]), "+f"(c[1]), "+f"(c[2]), "+f"(c[3])
        : "r"(a0), "r"(a1), "r"(a2), "r"(a3), "r"(b0), "r"(b1));
}

__device__ __forceinline__ void ldm_x4(uint32_t* r, uint32_t addr) {
    asm volatile("ldmatrix.sync.aligned.m8n8.x4.shared.b16 {%0,%1,%2,%3}, [%4];"
        : "=r"(r[0]), "=r"(r[1]), "=r"(r[2]), "=r"(r[3]) : "r"(addr));
}

__device__ __forceinline__ uint32_t smem_u32(const void* p) {
    uint32_t a;
    asm("{ .reg .u64 t; cvta.to.shared.u64 t, %1; cvt.u32.u64 %0, t; }" : "=r"(a) : "l"(p));
    return a;
}
__device__ __forceinline__ void cp16(uint32_t saddr, const void* gaddr) {
    asm volatile("cp.async.cg.shared.global [%0], [%1], 16;" :: "r"(saddr), "l"(gaddr) : "memory");
}
#define CP_COMMIT() asm volatile("cp.async.commit_group;" ::: "memory")
#define CP_WAIT1()  asm volatile("cp.async.wait_group 1;" ::: "memory")
#define CP_WAIT0()  asm volatile("cp.async.wait_group 0;" ::: "memory")

// ---------------- init: x -> hi/lo splits, weights pre-split, mask, z, cnt ---
__global__ void k_init(const float* __restrict__ x,
                       const float* w0, const float* w1, const float* w2,
                       const float* w3, const float* w4, const float* w5) {
    int i = blockIdx.x * blockDim.x + threadIdx.x;   // exactly NN*64 threads
    float2 v = reinterpret_cast<const float2*>(x)[i];
    uint32_t h = pack_bf16x2(v.x, v.y);
    uint32_t l = pack_bf16x2(v.x - bf_lo(h), v.y - bf_hi(h));
    g_xH[i] = h;
    g_xL[i] = l;
    if (i < NN) { g_nm[i] = 1; g_cnt[i] = 0; }
    if (i < BB * 256) g_z[i] = 0.f;
    if (i < 6 * 8192) {
        int m = i >> 13, j = i & 8191;
        const float* wp = (m == 0) ? w0 : (m == 1) ? w1 : (m == 2) ? w2
                         : (m == 3) ? w3 : (m == 4) ? w4 : w5;
        float2 w = reinterpret_cast<const float2*>(wp)[j];
        uint32_t wh = pack_bf16x2(w.x, w.y);
        uint32_t wl2 = pack_bf16x2(w.x - bf_lo(wh), w.y - bf_hi(wh));
        g_wH[m][j] = wh;
        g_wL[m][j] = wl2;
    }
}

__global__ void k_hist(const int* __restrict__ dst) {
    int e = blockIdx.x * blockDim.x + threadIdx.x;
    atomicAdd(&g_cnt[dst[e]], 1);
}

// ---------------- hierarchical scan (3 kernels) ----------------
__global__ void k_scan1() {
    __shared__ int sh[256];
    int b = blockIdx.x, t = threadIdx.x;
    int i = b * 256 + t;
    int c = g_cnt[i];
    sh[t] = c;
    __syncthreads();
#pragma unroll
    for (int off = 1; off < 256; off <<= 1) {
        int v = (t >= off) ? sh[t - off] : 0;
        __syncthreads();
        sh[t] += v;
        __syncthreads();
    }
    g_rowptr[i] = sh[t] - c;
    if (t == 255) g_bsum[b] = sh[t];
}

__global__ void k_scan2() {
    __shared__ int sh[256];
    int t = threadIdx.x;
    int c = g_bsum[t];
    sh[t] = c;
    __syncthreads();
#pragma unroll
    for (int off = 1; off < 256; off <<= 1) {
        int v = (t >= off) ? sh[t - off] : 0;
        __syncthreads();
        sh[t] += v;
        __syncthreads();
    }
    g_boff[t] = sh[t] - c;
}

__global__ void k_scan3() {
    int b = blockIdx.x, t = threadIdx.x;
    int i = b * 256 + t;
    int v = g_rowptr[i] + g_boff[b];
    g_rowptr[i] = v;
    g_fill[i] = v;
    if (i == 0) g_rowptr[NN] = EE;
}

__global__ void k_scatter(const int* __restrict__ src, const int* __restrict__ dst) {
    int e = blockIdx.x * blockDim.x + threadIdx.x;
    int p = atomicAdd(&g_fill[dst[e]], 1);
    g_csr[p] = src[e];
}

// ---------------- neighbor mean: branch-free (x of masked nodes is 0) -------
__global__ void k_aggregate() {
    int node = blockIdx.x * 8 + (threadIdx.x >> 5);
    int lane = threadIdx.x & 31;
    uint2* MH = reinterpret_cast<uint2*>(g_mH);
    uint2* ML = reinterpret_cast<uint2*>(g_mL);
    if (!g_nm[node]) {
        MH[node * 32 + lane] = make_uint2(0u, 0u);
        ML[node * 32 + lane] = make_uint2(0u, 0u);
        return;
    }
    int r0 = g_rowptr[node], r1 = g_rowptr[node + 1];
    const uint2* XH = reinterpret_cast<const uint2*>(g_xH);
    const uint2* XL = reinterpret_cast<const uint2*>(g_xL);
    float a0 = 0.f, a1 = 0.f, a2 = 0.f, a3 = 0.f;
    int deg = 0;
#pragma unroll 4
    for (int e = r0; e < r1; e++) {
        int s = g_csr[e];
        deg += (int)g_nm[s];                 // data, not branch
        uint2 h = XH[s * 32 + lane];         // masked rows are all-zero
        uint2 l = XL[s * 32 + lane];
        a0 += bf_lo(h.x) + bf_lo(l.x);
        a1 += bf_hi(h.x) + bf_hi(l.x);
        a2 += bf_lo(h.y) + bf_lo(l.y);
        a3 += bf_hi(h.y) + bf_hi(l.y);
    }
    float inv = 1.f / (float)(deg > 1 ? deg : 1);
    a0 *= inv; a1 *= inv; a2 *= inv; a3 *= inv;
    uint32_t h0 = pack_bf16x2(a0, a1);
    uint32_t h1 = pack_bf16x2(a2, a3);
    uint32_t l0 = pack_bf16x2(a0 - bf_lo(h0), a1 - bf_hi(h0));
    uint32_t l1 = pack_bf16x2(a2 - bf_lo(h1), a3 - bf_hi(h1));
    MH[node * 32 + lane] = make_uint2(h0, h1);
    ML[node * 32 + lane] = make_uint2(l0, l1);
}

// ---------------- 3xBF16 GEMM, cp.async double-buffered + ldmatrix ----------
// h = relu([mean|x] @ [wl|wr]^T + bl). 128x128 tile, K=256 in 8 chunks of 32.
#define BUF_U32   2560          // 128*20
#define STG_U32   10240         // 4 buffers
#define SMEM_GEMM 81920

__global__ __launch_bounds__(256, 2) void k_gemm(int layer, const float* __restrict__ bl)
{
    extern __shared__ __align__(16) uint32_t dsm[];
    __shared__ float sbias[128];
    uint32_t sb0 = smem_u32(dsm);

    int t = threadIdx.x;
    int lane = t & 31;
    int g = lane >> 2;      // 0..7
    int tq = lane & 3;      // 0..3
    int warp = t >> 5;
    int wm = warp >> 1;     // 0..3
    int wn = warp & 1;      // 0..1
    int base = blockIdx.x * 128;
    size_t bofs = (size_t)base * 64;

    if (t < 128) sbias[t] = bl[t];

    // copy slots
    int r0c = t >> 2, q4c = (t & 3) * 4;
    int r1c = r0c + 64;

    // ldmatrix lane addressing
    int q = lane >> 3;      // 0..3
    int lr = lane & 7;
    int a_row0 = wm * 32 + (q & 1) * 8 + lr;   // + mt*16
    int a_coladd = (q >> 1) * 4;
    int b_row0 = wn * 64 + (q >> 1) * 8 + lr;  // + (half*32 + j2*16)
    int b_coladd = (q & 1) * 4;

    float acc[2][8][4];
#pragma unroll
    for (int mt = 0; mt < 2; mt++)
#pragma unroll
        for (int nt = 0; nt < 8; nt++)
#pragma unroll
            for (int i = 0; i < 4; i++) acc[mt][nt][i] = 0.f;

    auto issue = [&](int c, int st) {
        const uint32_t* aH = (c < 4 ? g_mH : g_xH) + bofs + (c & 3) * 16;
        const uint32_t* aL = (c < 4 ? g_mL : g_xL) + bofs + (c & 3) * 16;
        const uint32_t* wH = g_wH[(layer << 1) | (c >> 2)] + (c & 3) * 16;
        const uint32_t* wLp = g_wL[(layer << 1) | (c >> 2)] + (c & 3) * 16;
        uint32_t sb = sb0 + st * (STG_U32 * 4);
        cp16(sb + (r0c * 20 + q4c) * 4,               aH + (size_t)r0c * 64 + q4c);
        cp16(sb + (r1c * 20 + q4c) * 4,               aH + (size_t)r1c * 64 + q4c);
        cp16(sb + (BUF_U32 + r0c * 20 + q4c) * 4,     aL + (size_t)r0c * 64 + q4c);
        cp16(sb + (BUF_U32 + r1c * 20 + q4c) * 4,     aL + (size_t)r1c * 64 + q4c);
        cp16(sb + (2 * BUF_U32 + r0c * 20 + q4c) * 4, wH + (size_t)r0c * 64 + q4c);
        cp16(sb + (2 * BUF_U32 + r1c * 20 + q4c) * 4, wH + (size_t)r1c * 64 + q4c);
        cp16(sb + (3 * BUF_U32 + r0c * 20 + q4c) * 4, wLp + (size_t)r0c * 64 + q4c);
        cp16(sb + (3 * BUF_U32 + r1c * 20 + q4c) * 4, wLp + (size_t)r1c * 64 + q4c);
        CP_COMMIT();
    };

    issue(0, 0);
    for (int c = 0; c < 8; c++) {
        int st = c & 1;
        if (c < 7) { issue(c + 1, st ^ 1); CP_WAIT1(); }
        else       { CP_WAIT0(); }
        __syncthreads();

        uint32_t bA_H = sb0 + st * (STG_U32 * 4);
        uint32_t bA_L = bA_H + BUF_U32 * 4;
        uint32_t bW_H = bA_H + 2 * BUF_U32 * 4;
        uint32_t bW_L = bA_H + 3 * BUF_U32 * 4;

#pragma unroll
        for (int ks = 0; ks < 2; ks++) {
            int cb = ks * 8;
            uint32_t aH[2][4], aL[2][4];
#pragma unroll
            for (int mt = 0; mt < 2; mt++) {
                uint32_t ar = ((uint32_t)((a_row0 + mt * 16) * 20 + cb + a_coladd)) * 4;
                ldm_x4(aH[mt], bA_H + ar);
                ldm_x4(aL[mt], bA_L + ar);
            }
#pragma unroll
            for (int half = 0; half < 2; half++) {
                uint32_t bh[8], blo[8];
#pragma unroll
                for (int j2 = 0; j2 < 2; j2++) {
                    uint32_t br = ((uint32_t)((b_row0 + half * 32 + j2 * 16) * 20 + cb + b_coladd)) * 4;
                    ldm_x4(&bh[j2 * 4],  bW_H + br);
                    ldm_x4(&blo[j2 * 4], bW_L + br);
                }
#pragma unroll
                for (int nt2 = 0; nt2 < 4; nt2++) {
                    int nt = half * 4 + nt2;
                    uint32_t b0h = bh[nt2 * 2], b1h = bh[nt2 * 2 + 1];
                    uint32_t b0l = blo[nt2 * 2], b1l = blo[nt2 * 2 + 1];
#pragma unroll
                    for (int mt = 0; mt < 2; mt++) {
                        mma_bf16(acc[mt][nt], aH[mt][0], aH[mt][1], aH[mt][2], aH[mt][3], b0h, b1h);
                        mma_bf16(acc[mt][nt], aH[mt][0], aH[mt][1], aH[mt][2], aH[mt][3], b0l, b1l);
                        mma_bf16(acc[mt][nt], aL[mt][0], aL[mt][1], aL[mt][2], aL[mt][3], b0h, b1h);
                    }
                }
            }
        }
        __syncthreads();
    }

    // epilogue: + bias, relu, store fp32 h
#pragma unroll
    for (int nt = 0; nt < 8; nt++) {
        int col = wn * 64 + nt * 8 + tq * 2;
        float bb0 = sbias[col];
        float bb1 = sbias[col + 1];
#pragma unroll
        for (int mt = 0; mt < 2; mt++) {
            int r = base + wm * 32 + mt * 16 + g;
            float2 o;
            o.x = fmaxf(acc[mt][nt][0] + bb0, 0.f);
            o.y = fmaxf(acc[mt][nt][1] + bb1, 0.f);
            *reinterpret_cast<float2*>(&g_h[(size_t)r * 128 + col]) = o;
            o.x = fmaxf(acc[mt][nt][2] + bb0, 0.f);
            o.y = fmaxf(acc[mt][nt][3] + bb1, 0.f);
            *reinterpret_cast<float2*>(&g_h[(size_t)(r + 8) * 128 + col]) = o;
        }
    }
}

// ---------------- top-k pool + fused readout + split-x output ----------------
__global__ __launch_bounds__(512) void k_pool(const float* __restrict__ pw, int k, float kf) {
    int g = blockIdx.x;
    int tid = threadIdx.x;

    __shared__ float w[128];
    __shared__ float scr[512];
    __shared__ float srt[512];
    __shared__ float fac[512];
    __shared__ unsigned char sel[512];
    __shared__ float smx[8][128];
    __shared__ float ssm[8][128];
    __shared__ float inv_norm;
    __shared__ int cgt;

    if (tid < 128) w[tid] = pw[tid];
    if (tid == 0) cgt = 0;
    __syncthreads();
    if (tid == 0) {
        float s = 0.f;
        for (int i = 0; i < 128; i++) s += w[i] * w[i];
        inv_norm = 1.f / (sqrtf(s) + 1e-16f);
    }
    __syncthreads();

    int wid = tid >> 5, lane = tid & 31;
    for (int n = wid; n < 512; n += 16) {
        int node = g * 512 + n;
        float4 p = reinterpret_cast<const float4*>(g_h + (size_t)node * 128)[lane];
        float4 ww = reinterpret_cast<const float4*>(w)[lane];
        float d = p.x * ww.x + p.y * ww.y + p.z * ww.z + p.w * ww.w;
#pragma unroll
        for (int off = 16; off > 0; off >>= 1)
            d += __shfl_xor_sync(0xffffffffu, d, off);
        if (lane == 0)
            scr[n] = g_nm[node] ? d * inv_norm : -INFINITY;
    }
    __syncthreads();
    srt[tid] = scr[tid];
    __syncthreads();

    for (int kk = 2; kk <= 512; kk <<= 1) {
        for (int j = kk >> 1; j > 0; j >>= 1) {
            int ixj = tid ^ j;
            if (ixj > tid) {
                float a = srt[tid], b = srt[ixj];
                bool asc = ((tid & kk) == 0);
                if ((a > b) == asc) { srt[tid] = b; srt[ixj] = a; }
            }
            __syncthreads();
        }
    }
    float thr = srt[512 - k];

    sel[tid] = (scr[tid] > thr) ? 1 : 0;
    if (scr[tid] > thr) atomicAdd(&cgt, 1);
    __syncthreads();
    if (tid == 0) {
        int need = k - cgt;
        for (int n = 0; n < 512 && need > 0; n++) {
            if (scr[n] == thr && !sel[n]) { sel[n] = 1; need--; }
        }
    }
    __syncthreads();

    fac[tid] = sel[tid] ? tanhf(scr[tid]) : 0.f;
    g_nm[g * 512 + tid] = sel[tid];
    __syncthreads();

    int c2 = tid & 63;
    int qd = tid >> 6;   // 0..7
    const float* hh = g_h + (size_t)g * 512 * 128;
    uint32_t* xh = g_xH + (size_t)g * 512 * 64;
    uint32_t* xl = g_xL + (size_t)g * 512 * 64;
    float mx0 = -INFINITY, sm0 = 0.f, mx1 = -INFINITY, sm1 = 0.f;
    for (int n = qd; n < 512; n += 8) {
        float f = fac[n];
        float v0 = hh[n * 128 + 2 * c2] * f;
        float v1 = hh[n * 128 + 2 * c2 + 1] * f;
        uint32_t H = pack_bf16x2(v0, v1);
        uint32_t L = pack_bf16x2(v0 - bf_lo(H), v1 - bf_hi(H));
        xh[n * 64 + c2] = H;
        xl[n * 64 + c2] = L;
        if (sel[n]) {
            mx0 = fmaxf(mx0, v0); sm0 += v0;
            mx1 = fmaxf(mx1, v1); sm1 += v1;
        }
    }
    smx[qd][2 * c2] = mx0; smx[qd][2 * c2 + 1] = mx1;
    ssm[qd][2 * c2] = sm0; ssm[qd][2 * c2 + 1] = sm1;
    __syncthreads();
    if (tid < 128) {
        float m = smx[0][tid], s = ssm[0][tid];
#pragma unroll
        for (int i = 1; i < 8; i++) { m = fmaxf(m, smx[i][tid]); s += ssm[i][tid]; }
        g_z[g * 256 + tid] += m;
        g_z[g * 256 + 128 + tid] += s / kf;
    }
}

// ---------------- MLP head ----------------
__global__ void k_mlp(const float* __restrict__ w1, const float* __restrict__ b1,
                      const float* __restrict__ w2, const float* __restrict__ b2,
                      const float* __restrict__ w3, const float* __restrict__ b3,
                      float* __restrict__ out)
{
    int g = blockIdx.x;
    int tid = threadIdx.x;
    __shared__ float z[256], t1[128], t2[64];
    z[tid] = g_z[g * 256 + tid];
    z[tid + 128] = g_z[g * 256 + 128 + tid];
    __syncthreads();
    {
        float s = b1[tid];
        for (int i = 0; i < 256; i++) s += z[i] * w1[tid * 256 + i];
        t1[tid] = fmaxf(s, 0.f);
    }
    __syncthreads();
    if (tid < 64) {
        float s = b2[tid];
        for (int i = 0; i < 128; i++) s += t1[i] * w2[tid * 128 + i];
        t2[tid] = fmaxf(s, 0.f);
    }
    __syncthreads();
    if (tid == 0) {
        float s = b3[0];
        for (int i = 0; i < 64; i++) s += t2[i] * w3[i];
        out[g] = 1.f / (1.f + expf(-s));
    }
}

// ---------------- launch ----------------
extern "C" void kernel_launch(void* const* d_in, const int* in_sizes, int n_in,
                              void* d_out, int out_size) {
    const float* x  = (const float*)d_in[0];
    const int*   ei = (const int*)d_in[1];
    const float* wl[3] = { (const float*)d_in[2], (const float*)d_in[6],  (const float*)d_in[10] };
    const float* bl[3] = { (const float*)d_in[3], (const float*)d_in[7],  (const float*)d_in[11] };
    const float* wr[3] = { (const float*)d_in[4], (const float*)d_in[8],  (const float*)d_in[12] };
    const float* pw[3] = { (const float*)d_in[5], (const float*)d_in[9],  (const float*)d_in[13] };
    const float* l1w = (const float*)d_in[14];
    const float* l1b = (const float*)d_in[15];
    const float* l2w = (const float*)d_in[16];
    const float* l2b = (const float*)d_in[17];
    const float* l3w = (const float*)d_in[18];
    const float* l3b = (const float*)d_in[19];
    float* out = (float*)d_out;

    const int KS[3] = { 410, 328, 263 };

    cudaFuncSetAttribute(k_gemm, cudaFuncAttributeMaxDynamicSharedMemorySize, SMEM_GEMM);

    k_init<<<NN * 64 / 256, 256>>>(x, wl[0], wr[0], wl[1], wr[1], wl[2], wr[2]);
    k_hist<<<EE / 256, 256>>>(ei + EE);
    k_scan1<<<256, 256>>>();
    k_scan2<<<1, 256>>>();
    k_scan3<<<256, 256>>>();
    k_scatter<<<EE / 256, 256>>>(ei, ei + EE);

    for (int l = 0; l < 3; l++) {
        k_aggregate<<<NN / 8, 256>>>();
        k_gemm<<<NN / 128, 256, SMEM_GEMM>>>(l, bl[l]);
        k_pool<<<BB, 512>>>(pw[l], KS[l], (float)KS[l]);
    }
    k_mlp<<<BB, 128>>>(l1w, l1b, l2w, l2b, l3w, l3b, out);
}